// round 1
// baseline (speedup 1.0000x reference)
#include <cuda_runtime.h>

typedef unsigned long long ull;

#define Bn 16
#define Fn 257
#define Tn 8000
#define NBn 64
#define CHUNK 1000
#define NCH 8
#define WARM 512
#define TTILE 128
#define FB_LD 66           // padded leading dim for transposed fb in smem

#define SMEM_BYTES ((Fn * TTILE + Fn * FB_LD) * (int)sizeof(float))  // 131584 + 67848 = 199432

// 131.6 MB scratch for vnr (device global: allocation-free)
__device__ __align__(128) float g_vnr[(size_t)Bn * Fn * Tn];

// ---------------- packed f32x2 helpers ----------------
__device__ __forceinline__ ull f2pack(float lo, float hi) {
    ull r; asm("mov.b64 %0, {%1, %2};" : "=l"(r) : "f"(lo), "f"(hi)); return r;
}
__device__ __forceinline__ ull f2fma(ull a, ull b, ull c) {
    ull d; asm("fma.rn.f32x2 %0, %1, %2, %3;" : "=l"(d) : "l"(a), "l"(b), "l"(c)); return d;
}
__device__ __forceinline__ void f2unpack(ull v, float& lo, float& hi) {
    asm("mov.b64 {%0, %1}, %2;" : "=f"(lo), "=f"(hi) : "l"(v));
}

// ---------------- scan step (contractive EMA) ----------------
__device__ __forceinline__ float nf_step(float x, float nf, float rise, float fall, float fl) {
    float a = (x > nf) ? rise : fall;
    nf = (1.0f - a) * nf + a * x;
    return fmaxf(nf, fl);
}

// ============================================================
// K1: chunked noise-floor scan -> vnr scratch
// One thread = one (chain, chunk). Chunks > 0 warm up WARM steps;
// contraction factor <= 0.9526 per step makes the warmup error ~2e-11.
// ============================================================
__global__ __launch_bounds__(256) void scan_kernel(
    const float* __restrict__ mag,
    const float* __restrict__ p_ns,
    const float* __restrict__ p_rr,
    const float* __restrict__ p_rf)
{
    int tid = blockIdx.x * 256 + threadIdx.x;
    if (tid >= Bn * Fn * NCH) return;
    int chunk = tid & (NCH - 1);
    int chain = tid >> 3;

    float rise = 1.0f / (1.0f + expf(-__ldg(p_rr)));
    float fall = 1.0f / (1.0f + expf(-__ldg(p_rf)));
    float ns   = fabsf(__ldg(p_ns));

    size_t base = (size_t)chain * Tn;
    const float4* gm = reinterpret_cast<const float4*>(mag + base);
    float4* gv = reinterpret_cast<float4*>(g_vnr + base);

    // init_min over first 20 frames, clipped at 1e-5
    float mn = 3.4e38f;
    #pragma unroll
    for (int i = 0; i < 20; ++i) mn = fminf(mn, __ldg(mag + base + i));
    mn = fmaxf(mn, 1e-5f);
    const float fl = 0.5f * mn;
    float nf = mn;

    int t0 = chunk * CHUNK;
    int tw = (chunk == 0) ? 0 : (t0 - WARM);

    // warmup (no output)
    for (int q = (tw >> 2); q < (t0 >> 2); ++q) {
        float4 v = gm[q];
        nf = nf_step(v.x, nf, rise, fall, fl);
        nf = nf_step(v.y, nf, rise, fall, fl);
        nf = nf_step(v.z, nf, rise, fall, fl);
        nf = nf_step(v.w, nf, rise, fall, fl);
    }

    // main chunk with software prefetch (2 float4 in flight)
    int q = t0 >> 2;
    int qend = q + (CHUNK / 4);
    float4 c0 = gm[q];
    float4 c1 = gm[q + 1];
    for (; q < qend; q += 2) {
        float4 n0 = c0, n1 = c1;
        if (q + 2 < qend) { n0 = gm[q + 2]; n1 = gm[q + 3]; }
        float4 o;
        nf = nf_step(c0.x, nf, rise, fall, fl); o.x = __fdividef(c0.x, fmaf(ns, nf, 1e-8f));
        nf = nf_step(c0.y, nf, rise, fall, fl); o.y = __fdividef(c0.y, fmaf(ns, nf, 1e-8f));
        nf = nf_step(c0.z, nf, rise, fall, fl); o.z = __fdividef(c0.z, fmaf(ns, nf, 1e-8f));
        nf = nf_step(c0.w, nf, rise, fall, fl); o.w = __fdividef(c0.w, fmaf(ns, nf, 1e-8f));
        gv[q] = o;
        nf = nf_step(c1.x, nf, rise, fall, fl); o.x = __fdividef(c1.x, fmaf(ns, nf, 1e-8f));
        nf = nf_step(c1.y, nf, rise, fall, fl); o.y = __fdividef(c1.y, fmaf(ns, nf, 1e-8f));
        nf = nf_step(c1.z, nf, rise, fall, fl); o.z = __fdividef(c1.z, fmaf(ns, nf, 1e-8f));
        nf = nf_step(c1.w, nf, rise, fall, fl); o.w = __fdividef(c1.w, fmaf(ns, nf, 1e-8f));
        gv[q + 1] = o;
        c0 = n0; c1 = n1;
    }
}

// ============================================================
// K2: band GEMM + tanh
// Block = (t-tile of 128, b). smem: vnr tile [257][128], fb^T [257][66 pad].
// Thread tile: 8n x 4t, packed f32x2 over n-pairs (fb pairs are contiguous
// in the transposed smem layout -> no per-FMA repacking of weights).
// ============================================================
extern __shared__ float k2_smem[];

__global__ __launch_bounds__(256) void band_kernel(
    const float* __restrict__ fb, float* __restrict__ out)
{
    float* vs = k2_smem;                 // [Fn][TTILE]
    float* fs = k2_smem + Fn * TTILE;    // [Fn][FB_LD] : fs[f*66 + n]
    const int b  = blockIdx.y;
    const int t0 = blockIdx.x * TTILE;
    const int tid = threadIdx.x;

    // load fb (coalesced global) and transpose into smem
    for (int i = tid; i < NBn * Fn; i += 256) {
        int n = i / Fn;
        int f = i - n * Fn;
        fs[f * FB_LD + n] = __ldg(fb + i);
    }
    // load vnr tile (coalesced along t), zero-pad past T
    const size_t vb = (size_t)b * Fn * Tn;
    for (int i = tid; i < Fn * (TTILE / 4); i += 256) {
        int f  = i >> 5;        // TTILE/4 == 32
        int tq = i & 31;
        int t  = t0 + tq * 4;
        float4 v = make_float4(0.f, 0.f, 0.f, 0.f);
        if (t < Tn) v = *reinterpret_cast<const float4*>(g_vnr + vb + (size_t)f * Tn + t);
        *reinterpret_cast<float4*>(vs + f * TTILE + tq * 4) = v;
    }
    __syncthreads();

    const int tn = tid >> 5;    // n-octet 0..7  -> n in [tn*8, tn*8+8)
    const int tt = tid & 31;    // t-quad  0..31 -> t in [tt*4, tt*4+4)

    ull acc[4][4];
    #pragma unroll
    for (int p = 0; p < 4; ++p)
        #pragma unroll
        for (int q = 0; q < 4; ++q) acc[p][q] = f2pack(0.f, 0.f);

    const float* vptr = vs + tt * 4;
    const float* fptr = fs + tn * 8;

    #pragma unroll 4
    for (int f = 0; f < Fn; ++f) {
        float4 v = *reinterpret_cast<const float4*>(vptr + f * TTILE);
        ull vd0 = f2pack(v.x, v.x);
        ull vd1 = f2pack(v.y, v.y);
        ull vd2 = f2pack(v.z, v.z);
        ull vd3 = f2pack(v.w, v.w);
        const float2* fp2 = reinterpret_cast<const float2*>(fptr + f * FB_LD);
        #pragma unroll
        for (int p = 0; p < 4; ++p) {
            float2 w = fp2[p];                 // fb[n=2p], fb[n=2p+1] (broadcast LDS)
            ull wp = f2pack(w.x, w.y);
            acc[p][0] = f2fma(vd0, wp, acc[p][0]);
            acc[p][1] = f2fma(vd1, wp, acc[p][1]);
            acc[p][2] = f2fma(vd2, wp, acc[p][2]);
            acc[p][3] = f2fma(vd3, wp, acc[p][3]);
        }
    }

    // epilogue: tanh(sum/10), coalesced float4 stores per n
    if (t0 + tt * 4 < Tn) {
        #pragma unroll
        for (int p = 0; p < 4; ++p) {
            float s0[4], s1[4];
            #pragma unroll
            for (int q = 0; q < 4; ++q) f2unpack(acc[p][q], s0[q], s1[q]);
            int n0 = tn * 8 + 2 * p;
            size_t ob = ((size_t)b * NBn + n0) * Tn + t0 + tt * 4;
            float4 o0, o1;
            o0.x = tanhf(0.1f * s0[0]); o0.y = tanhf(0.1f * s0[1]);
            o0.z = tanhf(0.1f * s0[2]); o0.w = tanhf(0.1f * s0[3]);
            o1.x = tanhf(0.1f * s1[0]); o1.y = tanhf(0.1f * s1[1]);
            o1.z = tanhf(0.1f * s1[2]); o1.w = tanhf(0.1f * s1[3]);
            *reinterpret_cast<float4*>(out + ob)      = o0;
            *reinterpret_cast<float4*>(out + ob + Tn) = o1;
        }
    }
}

// ============================================================
extern "C" void kernel_launch(void* const* d_in, const int* in_sizes, int n_in,
                              void* d_out, int out_size)
{
    const float* mag = (const float*)d_in[0];
    const float* fb  = (const float*)d_in[1];
    const float* ns  = (const float*)d_in[2];
    const float* rr  = (const float*)d_in[3];
    const float* rf  = (const float*)d_in[4];
    float* out = (float*)d_out;

    cudaFuncSetAttribute(band_kernel, cudaFuncAttributeMaxDynamicSharedMemorySize, SMEM_BYTES);

    int nthreads = Bn * Fn * NCH;
    scan_kernel<<<(nthreads + 255) / 256, 256>>>(mag, ns, rr, rf);

    dim3 grid((Tn + TTILE - 1) / TTILE, Bn);
    band_kernel<<<grid, 256, SMEM_BYTES>>>(fb, out);
}

// round 2
// speedup vs baseline: 1.2841x; 1.2841x over previous
#include <cuda_runtime.h>
#include <cuda_fp16.h>

typedef unsigned long long ull;

#define Bn 16
#define Fn 257
#define Tn 8000
#define NBn 64
#define CHUNK 400
#define NCH 20
#define WARM 256
#define TTILE 128
#define FB_LD 66

#define SMEM_BYTES ((Fn * TTILE + Fn * FB_LD) * (int)sizeof(float))  // 199432

// 65.8 MB fp16 scratch for 0.1*vnr (device global: allocation-free)
__device__ __align__(128) __half g_vnr[(size_t)Bn * Fn * Tn];

struct __align__(8) H4 { __half2 a, b; };

// ---------------- packed f32x2 helpers ----------------
__device__ __forceinline__ ull f2pack(float lo, float hi) {
    ull r; asm("mov.b64 %0, {%1, %2};" : "=l"(r) : "f"(lo), "f"(hi)); return r;
}
__device__ __forceinline__ ull f2fma(ull a, ull b, ull c) {
    ull d; asm("fma.rn.f32x2 %0, %1, %2, %3;" : "=l"(d) : "l"(a), "l"(b), "l"(c)); return d;
}
__device__ __forceinline__ void f2unpack(ull v, float& lo, float& hi) {
    asm("mov.b64 {%0, %1}, %2;" : "=f"(lo), "=f"(hi) : "l"(v));
}

// ---------------- branch-free contractive EMA step ----------------
// rise > fall  =>  nf' = max(nf+rise*d, nf+fall*d) selects rise iff d>0.
__device__ __forceinline__ float nf_step(float x, float nf, float rise, float fall, float fl) {
    float d  = x - nf;
    float cr = fmaf(rise, d, nf);
    float cf = fmaf(fall, d, nf);
    return fmaxf(fmaxf(cr, cf), fl);
}

// ============================================================
// K1: chunked noise-floor scan -> fp16 scratch (0.1 * vnr)
// 20 chunks/chain, 256-step warmup (error ~4e-6), prefetch depth 4.
// ============================================================
__global__ __launch_bounds__(256) void scan_kernel(
    const float* __restrict__ mag,
    const float* __restrict__ p_ns,
    const float* __restrict__ p_rr,
    const float* __restrict__ p_rf)
{
    int tid = blockIdx.x * 256 + threadIdx.x;
    if (tid >= Bn * Fn * NCH) return;
    int chunk = tid % NCH;
    int chain = tid / NCH;

    float rise = 1.0f / (1.0f + expf(-__ldg(p_rr)));
    float fall = 1.0f / (1.0f + expf(-__ldg(p_rf)));
    float ns   = fabsf(__ldg(p_ns));

    size_t base = (size_t)chain * Tn;
    const float4* gm = reinterpret_cast<const float4*>(mag + base);
    H4* gv = reinterpret_cast<H4*>(g_vnr + base);

    float mn = 3.4e38f;
    #pragma unroll
    for (int i = 0; i < 20; ++i) mn = fminf(mn, __ldg(mag + base + i));
    mn = fmaxf(mn, 1e-5f);
    const float fl = 0.5f * mn;
    float nf = mn;

    int t0 = chunk * CHUNK;
    int tw = (chunk == 0) ? 0 : (t0 - WARM);

    // warmup (no output)
    for (int q = (tw >> 2); q < (t0 >> 2); ++q) {
        float4 v = gm[q];
        nf = nf_step(v.x, nf, rise, fall, fl);
        nf = nf_step(v.y, nf, rise, fall, fl);
        nf = nf_step(v.z, nf, rise, fall, fl);
        nf = nf_step(v.w, nf, rise, fall, fl);
    }

    const int q0 = t0 >> 2;
    float4 b0 = gm[q0], b1 = gm[q0 + 1], b2 = gm[q0 + 2], b3 = gm[q0 + 3];

    #define EMIT4(c, idx) { \
        float o0, o1, o2, o3; \
        nf = nf_step(c.x, nf, rise, fall, fl); o0 = __fdividef(c.x, fmaf(ns, nf, 1e-8f)) * 0.1f; \
        nf = nf_step(c.y, nf, rise, fall, fl); o1 = __fdividef(c.y, fmaf(ns, nf, 1e-8f)) * 0.1f; \
        nf = nf_step(c.z, nf, rise, fall, fl); o2 = __fdividef(c.z, fmaf(ns, nf, 1e-8f)) * 0.1f; \
        nf = nf_step(c.w, nf, rise, fall, fl); o3 = __fdividef(c.w, fmaf(ns, nf, 1e-8f)) * 0.1f; \
        H4 st; st.a = __floats2half2_rn(o0, o1); st.b = __floats2half2_rn(o2, o3); \
        gv[idx] = st; }

    for (int i = 0; i < CHUNK / 4; i += 4) {
        float4 c0 = b0, c1 = b1, c2 = b2, c3 = b3;
        if (i + 8 <= CHUNK / 4) {
            b0 = gm[q0 + i + 4]; b1 = gm[q0 + i + 5];
            b2 = gm[q0 + i + 6]; b3 = gm[q0 + i + 7];
        }
        EMIT4(c0, q0 + i);
        EMIT4(c1, q0 + i + 1);
        EMIT4(c2, q0 + i + 2);
        EMIT4(c3, q0 + i + 3);
    }
    #undef EMIT4
}

// ============================================================
// K2: band GEMM + tanh (fp32 compute; fp16 scratch in, fp32 smem tile)
// Block = (t-tile 128, b). Thread tile 8n x 4t, packed f32x2 over n-pairs.
// Software-pipelined: next f's v + fb prefetched into registers.
// ============================================================
extern __shared__ float k2_smem[];

__global__ __launch_bounds__(256) void band_kernel(
    const float* __restrict__ fb, float* __restrict__ out)
{
    float* vs = k2_smem;                 // [Fn][TTILE] fp32
    float* fs = k2_smem + Fn * TTILE;    // [Fn][FB_LD] : fs[f*66 + n]
    const int b  = blockIdx.y;
    const int t0 = blockIdx.x * TTILE;
    const int tid = threadIdx.x;

    // fb transpose into smem (coalesced global read)
    for (int i = tid; i < NBn * Fn; i += 256) {
        int n = i / Fn;
        int f = i - n * Fn;
        fs[f * FB_LD + n] = __ldg(fb + i);
    }
    // vnr tile: fp16 global -> fp32 smem (8 halves per ldg.128)
    const size_t vb = (size_t)b * Fn * Tn;
    for (int i = tid; i < Fn * (TTILE / 8); i += 256) {
        int f = i >> 4;                  // TTILE/8 == 16
        int c = (i & 15) * 8;
        int t = t0 + c;
        float4 lo = make_float4(0.f, 0.f, 0.f, 0.f);
        float4 hi = lo;
        if (t < Tn) {
            uint4 r = *reinterpret_cast<const uint4*>(g_vnr + vb + (size_t)f * Tn + t);
            __half2 h0 = *reinterpret_cast<__half2*>(&r.x);
            __half2 h1 = *reinterpret_cast<__half2*>(&r.y);
            __half2 h2 = *reinterpret_cast<__half2*>(&r.z);
            __half2 h3 = *reinterpret_cast<__half2*>(&r.w);
            float2 f0 = __half22float2(h0), f1 = __half22float2(h1);
            float2 f2 = __half22float2(h2), f3 = __half22float2(h3);
            lo = make_float4(f0.x, f0.y, f1.x, f1.y);
            hi = make_float4(f2.x, f2.y, f3.x, f3.y);
        }
        *reinterpret_cast<float4*>(vs + f * TTILE + c)     = lo;
        *reinterpret_cast<float4*>(vs + f * TTILE + c + 4) = hi;
    }
    __syncthreads();

    const int tn = tid >> 5;    // n-octet
    const int tt = tid & 31;    // t-quad

    ull acc[4][4];
    #pragma unroll
    for (int p = 0; p < 4; ++p)
        #pragma unroll
        for (int q = 0; q < 4; ++q) acc[p][q] = f2pack(0.f, 0.f);

    const float* vrow = vs + tt * 4;
    const float* frow = fs + tn * 8;

    float4 v = *reinterpret_cast<const float4*>(vrow);
    float2 w0, w1, w2, w3;
    {
        const float2* fp2 = reinterpret_cast<const float2*>(frow);
        w0 = fp2[0]; w1 = fp2[1]; w2 = fp2[2]; w3 = fp2[3];
    }

    #pragma unroll 4
    for (int f = 0; f < Fn; ++f) {
        int fnext = (f + 1 < Fn) ? f + 1 : Fn - 1;
        float4 vn = *reinterpret_cast<const float4*>(vrow + fnext * TTILE);
        const float2* fp2 = reinterpret_cast<const float2*>(frow + fnext * FB_LD);
        float2 nw0 = fp2[0], nw1 = fp2[1], nw2 = fp2[2], nw3 = fp2[3];

        ull vd0 = f2pack(v.x, v.x);
        ull vd1 = f2pack(v.y, v.y);
        ull vd2 = f2pack(v.z, v.z);
        ull vd3 = f2pack(v.w, v.w);
        ull wp0 = f2pack(w0.x, w0.y);
        ull wp1 = f2pack(w1.x, w1.y);
        ull wp2 = f2pack(w2.x, w2.y);
        ull wp3 = f2pack(w3.x, w3.y);

        acc[0][0] = f2fma(vd0, wp0, acc[0][0]);
        acc[0][1] = f2fma(vd1, wp0, acc[0][1]);
        acc[0][2] = f2fma(vd2, wp0, acc[0][2]);
        acc[0][3] = f2fma(vd3, wp0, acc[0][3]);
        acc[1][0] = f2fma(vd0, wp1, acc[1][0]);
        acc[1][1] = f2fma(vd1, wp1, acc[1][1]);
        acc[1][2] = f2fma(vd2, wp1, acc[1][2]);
        acc[1][3] = f2fma(vd3, wp1, acc[1][3]);
        acc[2][0] = f2fma(vd0, wp2, acc[2][0]);
        acc[2][1] = f2fma(vd1, wp2, acc[2][1]);
        acc[2][2] = f2fma(vd2, wp2, acc[2][2]);
        acc[2][3] = f2fma(vd3, wp2, acc[2][3]);
        acc[3][0] = f2fma(vd0, wp3, acc[3][0]);
        acc[3][1] = f2fma(vd1, wp3, acc[3][1]);
        acc[3][2] = f2fma(vd2, wp3, acc[3][2]);
        acc[3][3] = f2fma(vd3, wp3, acc[3][3]);

        v = vn;
        w0 = nw0; w1 = nw1; w2 = nw2; w3 = nw3;
    }

    // epilogue: tanh(sum) (the /10 was folded into the scratch)
    if (t0 + tt * 4 < Tn) {
        #pragma unroll
        for (int p = 0; p < 4; ++p) {
            float s0[4], s1[4];
            #pragma unroll
            for (int q = 0; q < 4; ++q) f2unpack(acc[p][q], s0[q], s1[q]);
            int n0 = tn * 8 + 2 * p;
            size_t ob = ((size_t)b * NBn + n0) * Tn + t0 + tt * 4;
            float4 o0, o1;
            o0.x = tanhf(s0[0]); o0.y = tanhf(s0[1]);
            o0.z = tanhf(s0[2]); o0.w = tanhf(s0[3]);
            o1.x = tanhf(s1[0]); o1.y = tanhf(s1[1]);
            o1.z = tanhf(s1[2]); o1.w = tanhf(s1[3]);
            *reinterpret_cast<float4*>(out + ob)      = o0;
            *reinterpret_cast<float4*>(out + ob + Tn) = o1;
        }
    }
}

// ============================================================
extern "C" void kernel_launch(void* const* d_in, const int* in_sizes, int n_in,
                              void* d_out, int out_size)
{
    const float* mag = (const float*)d_in[0];
    const float* fb  = (const float*)d_in[1];
    const float* ns  = (const float*)d_in[2];
    const float* rr  = (const float*)d_in[3];
    const float* rf  = (const float*)d_in[4];
    float* out = (float*)d_out;

    cudaFuncSetAttribute(band_kernel, cudaFuncAttributeMaxDynamicSharedMemorySize, SMEM_BYTES);

    int nthreads = Bn * Fn * NCH;
    scan_kernel<<<(nthreads + 255) / 256, 256>>>(mag, ns, rr, rf);

    dim3 grid((Tn + TTILE - 1) / TTILE, Bn);
    band_kernel<<<grid, 256, SMEM_BYTES>>>(fb, out);
}